// round 4
// baseline (speedup 1.0000x reference)
#include <cuda_runtime.h>
#include <cuda_fp16.h>
#include <cstdint>

// ============================ constants ============================

static constexpr int B_ROWS = 65536;   // query rows
static constexpr int D_DIM  = 512;     // feature dim
static constexpr int C_DIM  = 1024;    // memory slots

static constexpr int MT = 128;         // CTA tile M
static constexpr int NT = 128;         // CTA tile N
static constexpr int KC = 64;          // K per smem stage

static constexpr uint32_t STAGE_BYTES = (MT * KC + NT * KC) * 2;  // 32768
static constexpr uint32_t SMEM_TOTAL  = 2 * STAGE_BYTES + 512;    // + rowinv[128]

// ============================ device scratch ============================

__device__ __align__(1024) __half g_qn[(size_t)B_ROWS * D_DIM];     // 64 MB
__device__ __align__(1024) __half g_kn[(size_t)C_DIM * D_DIM];      // 1 MB
__device__ __align__(1024) __half g_valT[(size_t)C_DIM * C_DIM];    // 2 MB
__device__ __align__(1024) __half g_sharp[(size_t)B_ROWS * C_DIM];  // 128 MB

// ============================ helpers ============================

__device__ __forceinline__ uint32_t smem_to_u32(const void* smem_ptr) {
    uint32_t addr;
    asm("{ .reg .u64 tmp; cvta.to.shared.u64 tmp, %1; cvt.u32.u64 %0, tmp; }"
        : "=r"(addr) : "l"(smem_ptr));
    return addr;
}

__device__ __forceinline__ void cp_async16(uint32_t dst, const void* src) {
    asm volatile("cp.async.cg.shared.global [%0], [%1], 16;"
                 :: "r"(dst), "l"(src) : "memory");
}

__device__ __forceinline__ void ldmatrix_x4(uint32_t* r, uint32_t addr) {
    asm volatile("ldmatrix.sync.aligned.m8n8.x4.shared.b16 {%0,%1,%2,%3}, [%4];"
                 : "=r"(r[0]), "=r"(r[1]), "=r"(r[2]), "=r"(r[3]) : "r"(addr));
}

__device__ __forceinline__ void mma16816(float* c, const uint32_t* a,
                                         uint32_t b0, uint32_t b1) {
    asm volatile(
        "mma.sync.aligned.m16n8k16.row.col.f32.f16.f16.f32 "
        "{%0,%1,%2,%3}, {%4,%5,%6,%7}, {%8,%9}, {%0,%1,%2,%3};"
        : "+f"(c[0]), "+f"(c[1]), "+f"(c[2]), "+f"(c[3])
        : "r"(a[0]), "r"(a[1]), "r"(a[2]), "r"(a[3]), "r"(b0), "r"(b1));
}

__device__ __forceinline__ float softabs_f(float x) {
    // sigmoid(10x - 5) + sigmoid(-10x - 5)
    const float t = 10.f * x;
    const float a = 1.f / (1.f + __expf(5.f - t));
    const float b = 1.f / (1.f + __expf(5.f + t));
    return a + b;
}

// swizzled smem byte offset for element (row, k) in a [rows][64]-half tile
// (row stride 128B; 16B chunk index XORed with row&7 -> conflict-free ldmatrix)
__device__ __forceinline__ uint32_t swz_off(int row, int kchunk) {
    return (uint32_t)(row * 128 + ((kchunk ^ (row & 7)) << 4));
}

// ============================ prep kernels ============================

// L2-normalize rows of a [rows x 512] fp32 matrix into fp16.
__global__ void __launch_bounds__(256) prep_norm_kernel(
    const float* __restrict__ src, __half* __restrict__ dst)
{
    const int wid  = threadIdx.x >> 5;
    const int lane = threadIdx.x & 31;
    const size_t row = (size_t)blockIdx.x * 8 + wid;

    const float4* s4 = (const float4*)(src + row * D_DIM);
    float4 v[4];
    float ss = 0.f;
#pragma unroll
    for (int i = 0; i < 4; i++) {
        v[i] = s4[lane + 32 * i];
        ss += v[i].x * v[i].x + v[i].y * v[i].y + v[i].z * v[i].z + v[i].w * v[i].w;
    }
#pragma unroll
    for (int o = 16; o > 0; o >>= 1) ss += __shfl_xor_sync(0xffffffffu, ss, o);
    const float inv = rsqrtf(ss + 1e-12f);

    uint2* d2 = (uint2*)(dst + row * D_DIM);
#pragma unroll
    for (int i = 0; i < 4; i++) {
        __half2 a = __floats2half2_rn(v[i].x * inv, v[i].y * inv);
        __half2 b = __floats2half2_rn(v[i].z * inv, v[i].w * inv);
        d2[lane + 32 * i] = make_uint2(*reinterpret_cast<uint32_t*>(&a),
                                       *reinterpret_cast<uint32_t*>(&b));
    }
}

// Transpose + fp16-convert val_mem (1024x1024 fp32) -> g_valT[n][c] = val[c][n]
__global__ void __launch_bounds__(256) transpose_val_kernel(const float* __restrict__ v)
{
    __shared__ float t[32][33];
    const int tx = threadIdx.x & 31;
    const int ty = threadIdx.x >> 5;
    const int x  = blockIdx.x * 32 + tx;
    const int y0 = blockIdx.y * 32 + ty;
#pragma unroll
    for (int i = 0; i < 4; i++)
        t[ty + i * 8][tx] = v[(size_t)(y0 + i * 8) * C_DIM + x];
    __syncthreads();
    const int x2 = blockIdx.y * 32 + tx;
    const int y2 = blockIdx.x * 32 + ty;
#pragma unroll
    for (int i = 0; i < 4; i++)
        g_valT[(size_t)(y2 + i * 8) * C_DIM + x2] = __float2half(t[tx][ty + i * 8]);
}

// ============================ GEMM ============================
// D[m][n] = sum_k A[m][k]*B[n][k], fp16 in / fp32 accum via mma.sync m16n8k16.
// EPI==0: epilogue = softabs(acc) -> g_sharp (fp16)
// EPI==1: rowsum of A computed on the fly; epilogue = acc / rowsum -> out (fp32)
template<int KTOT, int EPI>
__global__ void __launch_bounds__(256, 2)
gemm_kernel(const __half* __restrict__ A, const __half* __restrict__ B,
            float* __restrict__ out)
{
    extern __shared__ char smem[];
    const uint32_t sbase = smem_to_u32(smem);
    const int tid  = threadIdx.x;
    const int lane = tid & 31;
    const int wid  = tid >> 5;
    const int warp_m = wid >> 2;      // 0..1  (64 rows each)
    const int warp_n = wid & 3;       // 0..3  (32 cols each)
    const int mbase = blockIdx.y * MT;
    const int nbase = blockIdx.x * NT;

    constexpr int NCH = KTOT / KC;

    float acc[4][4][4];
#pragma unroll
    for (int a = 0; a < 4; a++)
#pragma unroll
        for (int b = 0; b < 4; b++)
#pragma unroll
            for (int c = 0; c < 4; c++) acc[a][b][c] = 0.f;

    float rsum = 0.f;

    // ---- stage loader: A tile [128][64] + B tile [128][64], swizzled ----
    auto load_stage = [&](int kc, int s) {
        const uint32_t sA = sbase + (uint32_t)s * STAGE_BYTES;
        const uint32_t sB = sA + MT * KC * 2;
#pragma unroll
        for (int i = 0; i < 4; i++) {
            const int idx = tid + i * 256;
            const int r = idx >> 3, c = idx & 7;
            cp_async16(sA + swz_off(r, c),
                       A + (size_t)(mbase + r) * KTOT + kc * KC + c * 8);
        }
#pragma unroll
        for (int i = 0; i < 4; i++) {
            const int idx = tid + i * 256;
            const int r = idx >> 3, c = idx & 7;
            cp_async16(sB + swz_off(r, c),
                       B + (size_t)(nbase + r) * KTOT + kc * KC + c * 8);
        }
        asm volatile("cp.async.commit_group;" ::: "memory");
    };

    // ---- per-stage compute ----
    auto mma_stage = [&](int s) {
        const uint32_t sA = sbase + (uint32_t)s * STAGE_BYTES;
        const uint32_t sB = sA + MT * KC * 2;

        if (EPI == 1) {
            // deterministic rowsum of the fp16 A tile: 2 threads / row
            const int row = tid >> 1, hf = tid & 1;
            const char* base = smem + s * STAGE_BYTES + row * 128;
#pragma unroll
            for (int j = 0; j < 4; j++) {
                const int ch = (hf * 4 + j) ^ (row & 7);
                uint4 v = *(const uint4*)(base + ch * 16);
                const __half2* h2 = (const __half2*)&v;
#pragma unroll
                for (int q = 0; q < 4; q++) {
                    float2 f = __half22float2(h2[q]);
                    rsum += f.x + f.y;
                }
            }
        }

#pragma unroll
        for (int ks = 0; ks < 4; ks++) {
            const int lrow15 = lane & 15;
            const int kch = ks * 2 + (lane >> 4);   // 16B chunk index of this lane
            uint32_t bf[2][4];
#pragma unroll
            for (int p = 0; p < 2; p++) {
                const int row = warp_n * 32 + p * 16 + lrow15;
                ldmatrix_x4(bf[p], sB + swz_off(row, kch));
            }
#pragma unroll
            for (int mt = 0; mt < 4; mt++) {
                const int row = warp_m * 64 + mt * 16 + lrow15;
                uint32_t af[4];
                ldmatrix_x4(af, sA + swz_off(row, kch));
#pragma unroll
                for (int nt = 0; nt < 4; nt++) {
                    const int p = nt >> 1, lo = nt & 1;
                    mma16816(acc[mt][nt], af, bf[p][lo], bf[p][2 + lo]);
                }
            }
        }
    };

    // ---- pipelined main loop (2-stage double buffer) ----
    load_stage(0, 0);
#pragma unroll 1
    for (int kc = 0; kc < NCH - 1; kc++) {
        load_stage(kc + 1, (kc + 1) & 1);
        asm volatile("cp.async.wait_group 1;" ::: "memory");
        __syncthreads();
        mma_stage(kc & 1);
        __syncthreads();
    }
    asm volatile("cp.async.wait_group 0;" ::: "memory");
    __syncthreads();
    mma_stage((NCH - 1) & 1);

    // ---- rowsum finalize (EPI1) ----
    float* rowinv = (float*)(smem + 2 * STAGE_BYTES);
    if (EPI == 1) {
        const float tot = rsum + __shfl_xor_sync(0xffffffffu, rsum, 1);
        __syncthreads();                     // all reads of last stage done
        if ((tid & 1) == 0) rowinv[tid >> 1] = 1.0f / tot;
        __syncthreads();
    }

    // ---- epilogue ----
    const int g   = lane >> 2;     // 0..7
    const int tig = lane & 3;      // 0..3
#pragma unroll
    for (int mt = 0; mt < 4; mt++) {
        const int rl = warp_m * 64 + mt * 16 + g;        // local row (and +8)
        const int rg = mbase + rl;
        if (EPI == 0) {
#pragma unroll
            for (int nt = 0; nt < 4; nt++) {
                const int n = nbase + warp_n * 32 + nt * 8 + tig * 2;
                __half2 h0 = __floats2half2_rn(softabs_f(acc[mt][nt][0]),
                                               softabs_f(acc[mt][nt][1]));
                __half2 h1 = __floats2half2_rn(softabs_f(acc[mt][nt][2]),
                                               softabs_f(acc[mt][nt][3]));
                *(__half2*)(g_sharp + (size_t)rg * C_DIM + n) = h0;
                *(__half2*)(g_sharp + (size_t)(rg + 8) * C_DIM + n) = h1;
            }
        } else {
            const float i0 = rowinv[rl];
            const float i1 = rowinv[rl + 8];
#pragma unroll
            for (int nt = 0; nt < 4; nt++) {
                const int n = nbase + warp_n * 32 + nt * 8 + tig * 2;
                *(float2*)(out + (size_t)rg * C_DIM + n) =
                    make_float2(acc[mt][nt][0] * i0, acc[mt][nt][1] * i0);
                *(float2*)(out + (size_t)(rg + 8) * C_DIM + n) =
                    make_float2(acc[mt][nt][2] * i1, acc[mt][nt][3] * i1);
            }
        }
    }
}

// ============================ launcher ============================

extern "C" void kernel_launch(void* const* d_in, const int* in_sizes, int n_in,
                              void* d_out, int out_size)
{
    const float* q  = (const float*)d_in[0];   // (65536, 512)
    const float* km = (const float*)d_in[1];   // (1024, 512)
    const float* vm = (const float*)d_in[2];   // (1024, 1024)
    float* out = (float*)d_out;                // (65536, 1024)

    void *p_qn = nullptr, *p_kn = nullptr, *p_valT = nullptr, *p_sharp = nullptr;
    cudaGetSymbolAddress(&p_qn, g_qn);
    cudaGetSymbolAddress(&p_kn, g_kn);
    cudaGetSymbolAddress(&p_valT, g_valT);
    cudaGetSymbolAddress(&p_sharp, g_sharp);

    cudaFuncSetAttribute(gemm_kernel<512, 0>,
                         cudaFuncAttributeMaxDynamicSharedMemorySize, SMEM_TOTAL);
    cudaFuncSetAttribute(gemm_kernel<1024, 1>,
                         cudaFuncAttributeMaxDynamicSharedMemorySize, SMEM_TOTAL);

    // 1) normalize keys -> fp16
    prep_norm_kernel<<<C_DIM / 8, 256>>>(km, (__half*)p_kn);
    // 2) transpose + convert val_mem -> fp16
    transpose_val_kernel<<<dim3(32, 32), 256>>>(vm);
    // 3) normalize queries -> fp16
    prep_norm_kernel<<<B_ROWS / 8, 256>>>(q, (__half*)p_qn);
    // 4) sim GEMM + softabs -> g_sharp        grid: (N tiles, M tiles)
    gemm_kernel<512, 0><<<dim3(C_DIM / NT, B_ROWS / MT), 256, SMEM_TOTAL>>>(
        (const __half*)p_qn, (const __half*)p_kn, nullptr);
    // 5) value GEMM (+on-the-fly rowsum) + normalize -> out
    gemm_kernel<1024, 1><<<dim3(C_DIM / NT, B_ROWS / MT), 256, SMEM_TOTAL>>>(
        (const __half*)p_sharp, (const __half*)p_valT, out);
}